// round 17
// baseline (speedup 1.0000x reference)
#include <cuda_runtime.h>
#include <cooperative_groups.h>

namespace cg = cooperative_groups;

#define N_NODES 100000
#define N_EDGES 800000
#define DIN 16
#define H 128
#define OUTD 3
#define SLOPE 0.01f

typedef unsigned long long u64;

// ---------------- packed f32x2 helpers (kept for Wc packing convenience) ----
__device__ __forceinline__ u64 pk2(float lo, float hi) {
    u64 r; asm("mov.b64 %0, {%1, %2};" : "=l"(r) : "f"(lo), "f"(hi)); return r;
}

// ---------------- scratch (no allocations; zero-initialized at load) -------
// INVARIANT: g_deg and g_acc are all-zero at kernel_launch entry; the final
// phase restores this, so graph replays are deterministic.
__device__ __align__(16) float  g_deg[N_NODES];       // in-degree (float)
__device__ __align__(16) float  g_dinv[N_NODES];      // rsqrt(deg+1)
__device__ __align__(16) float4 g_z4 [N_NODES];       // p = (dinv*z, dinv)
__device__ __align__(16) float4 g_acc[N_NODES];       // edge accumulator (both passes)
__device__ __align__(16) float4 g_z14[N_NODES];       // q = (dinv*z1, 0)
__device__ __align__(16) float  g_a1 [N_NODES];       // (A·1)_d
__device__ __align__(16) float  g_Wc [H * OUTD];      // W1 @ W2 @ W_out
__device__ float g_v[OUTD];                           // b1 @ W2 @ W_out
__device__ float g_c[OUTD];                           // b2 @ W_out + b_out

// published pointers (used by the non-cooperative fallback path)
__device__ const void*  g_ei_ptr;
__device__ int          g_ei64;
__device__ const float* g_feat_p;

// ---------------- shared ident logic ----------------
// Sample int32 WORDS (in-bounds for either dtype).
//  edge_index(int32): every word in [0, N)                      -> edge, !is64
//  edge_index(int64): words alternate (index, 0), all in [0, N) -> edge,  is64
//  feature (float32): N(0,1) bits land in [0,100000) only for |f|<1.4e-40
// Block-collective: all threads participate; result in sOut (shared).
//   sOut[0] = 1 if A is edge_index else 0 ; sOut[1] = is64 flag of chosen buffer
__device__ __forceinline__ void ident_block(const int* A, const int* B, int* sflags) {
    int t = threadIdx.x;
    if (t < 4) sflags[t] = 1;
    __syncthreads();
    if (t < 256) {
        int idx = t * 6247 + 2;                       // even, < 1,600,000
        int a0 = A[idx], a1v = A[idx + 1];
        int b0 = B[idx], b1v = B[idx + 1];
        if ((unsigned)a0 >= N_NODES || (unsigned)a1v >= N_NODES) atomicAnd(&sflags[0], 0);
        if ((unsigned)b0 >= N_NODES || (unsigned)b1v >= N_NODES) atomicAnd(&sflags[1], 0);
        if (a1v != 0) atomicAnd(&sflags[2], 0);
        if (b1v != 0) atomicAnd(&sflags[3], 0);
    }
    __syncthreads();
}

__device__ __forceinline__ int2 load_edge_p(const void* ei, int is64, int e) {
    if (is64) {
        const long long* p = (const long long*)ei;
        return make_int2((int)p[e], (int)p[N_EDGES + e]);
    } else {
        const int* p = (const int*)ei;
        return make_int2(p[e], p[N_EDGES + e]);
    }
}

// ---------------- phase bodies (device functions, shared by both paths) ----

// feat for one node: z = LeakyReLU(F_row@Win+bin) @ Wc, pack p = (dv*z, dv)
__device__ __forceinline__ void feat_node(int i, const float* feat,
                                          const float* sWin, const float* sbin,
                                          const float* sWc) {
    float dv = rsqrtf(g_deg[i] + 1.0f);
    g_dinv[i] = dv;

    const float4* Fr = (const float4*)(feat + (size_t)i * DIN);
    float4 fa = Fr[0], fb = Fr[1], fc = Fr[2], fd = Fr[3];
    float f[16] = { fa.x, fa.y, fa.z, fa.w, fb.x, fb.y, fb.z, fb.w,
                    fc.x, fc.y, fc.z, fc.w, fd.x, fd.y, fd.z, fd.w };

    float acc0 = 0.0f, acc1 = 0.0f, acc2 = 0.0f;

    #pragma unroll 4
    for (int j0 = 0; j0 < H; j0 += 4) {
        float4 h = *(const float4*)&sbin[j0];
        #pragma unroll
        for (int k = 0; k < DIN; k++) {
            float4 w = *(const float4*)&sWin[k * H + j0];
            h.x = fmaf(f[k], w.x, h.x);
            h.y = fmaf(f[k], w.y, h.y);
            h.z = fmaf(f[k], w.z, h.z);
            h.w = fmaf(f[k], w.w, h.w);
        }
        h.x = h.x > 0.0f ? h.x : SLOPE * h.x;
        h.y = h.y > 0.0f ? h.y : SLOPE * h.y;
        h.z = h.z > 0.0f ? h.z : SLOPE * h.z;
        h.w = h.w > 0.0f ? h.w : SLOPE * h.w;
        const float4* wc = (const float4*)&sWc[j0 * 3];
        float4 wa = wc[0], wb = wc[1], wd = wc[2];
        acc0 = fmaf(h.x, wa.x, fmaf(h.y, wa.w, fmaf(h.z, wb.z, fmaf(h.w, wd.y, acc0))));
        acc1 = fmaf(h.x, wa.y, fmaf(h.y, wb.x, fmaf(h.z, wb.w, fmaf(h.w, wd.z, acc1))));
        acc2 = fmaf(h.x, wa.z, fmaf(h.y, wb.y, fmaf(h.z, wd.x, fmaf(h.w, wd.w, acc2))));
    }
    g_z4[i] = make_float4(acc0 * dv, acc1 * dv, acc2 * dv, dv);
}

__device__ __forceinline__ void mid_node(int i) {
    float dv = g_dinv[i];
    float4 acc = g_acc[i];
    float4 p   = g_z4[i];
    float z1x = dv * (acc.x + p.x);
    float z1y = dv * (acc.y + p.y);
    float z1z = dv * (acc.z + p.z);
    g_a1[i]  = dv * (acc.w + p.w);
    g_z14[i] = make_float4(dv * z1x, dv * z1y, dv * z1z, 0.0f);
    g_acc[i] = make_float4(0.0f, 0.0f, 0.0f, 0.0f);
}

__device__ __forceinline__ void final_node(int i, float* out) {
    float dv = g_dinv[i];
    float4 acc = g_acc[i];
    float4 q   = g_z14[i];
    float a    = g_a1[i];
    out[3 * i + 0] = dv * (acc.x + q.x) + a * g_v[0] + g_c[0];
    out[3 * i + 1] = dv * (acc.y + q.y) + a * g_v[1] + g_c[1];
    out[3 * i + 2] = dv * (acc.z + q.z) + a * g_v[2] + g_c[2];
    g_deg[i] = 0.0f;                                  // restore invariant
    g_acc[i] = make_float4(0.0f, 0.0f, 0.0f, 0.0f);
}

// constants: U = W2@Wout ; Wc = W1@U ; v = b1@U ; c = b2@Wout+bout
// block-collective, any blockDim >= 256; scratch = 768 floats of shared
__device__ __forceinline__ void constants_block(
        const float* W1, const float* W2, const float* Wout,
        const float* b1, const float* b2, const float* bout,
        float* sWo, float* sU) {
    int t = threadIdx.x;
    for (int j = t; j < H * OUTD; j += blockDim.x) sWo[j] = Wout[j];
    __syncthreads();
    for (int idx = t; idx < H * OUTD; idx += blockDim.x) {
        int k = idx / 3, o = idx % 3;
        float s = 0.0f;
        #pragma unroll 8
        for (int j = 0; j < H; j++) s = fmaf(W2[k * H + j], sWo[j * 3 + o], s);
        sU[idx] = s;
    }
    __syncthreads();
    for (int idx = t; idx < H * OUTD; idx += blockDim.x) {
        int r = idx / 3, o = idx % 3;
        float s = 0.0f;
        #pragma unroll 8
        for (int k = 0; k < H; k++) s = fmaf(W1[r * H + k], sU[k * 3 + o], s);
        g_Wc[idx] = s;
    }
    if (t < 3) {
        float s = 0.0f;
        for (int k = 0; k < H; k++) s = fmaf(b1[k], sU[k * 3 + t], s);
        g_v[t] = s;
    } else if (t < 6) {
        int o = t - 3;
        float s = 0.0f;
        for (int j = 0; j < H; j++) s = fmaf(b2[j], sWo[j * 3 + o], s);
        g_c[o] = s + bout[o];
    }
}

// ================= cooperative mega-kernel =================
__global__ void __launch_bounds__(256)
k_mega(const int* A, const int* B,
       const float* __restrict__ W1, const float* __restrict__ W2,
       const float* __restrict__ Wout,
       const float* __restrict__ b1, const float* __restrict__ b2,
       const float* __restrict__ bout,
       const float* __restrict__ Win, const float* __restrict__ bin,
       float* __restrict__ out) {
    cg::grid_group grid = cg::this_grid();
    __shared__ __align__(16) float sWin[DIN * H];     // 8KB; phase-A scratch too
    __shared__ __align__(16) float sbin[H];
    __shared__ __align__(16) float sWc[H * OUTD];
    __shared__ int sflags[4];

    int t = threadIdx.x;
    int bid = blockIdx.x;
    int nb  = gridDim.x;
    int gstride = nb * blockDim.x;

    // per-block ident (registers/shared; cached in L2 after first block)
    ident_block(A, B, sflags);
    const void* ei;  int is64;  const float* feat;
    if (sflags[0] && !sflags[1]) { ei = A; is64 = sflags[2]; feat = (const float*)B; }
    else                         { ei = B; is64 = sflags[3]; feat = (const float*)A; }
    __syncthreads();                                   // sflags reuse-safe

    // ---- phase A: block 0 constants (sWin as scratch), others degree count
    if (bid == 0) {
        constants_block(W1, W2, Wout, b1, b2, bout, sWin, sWin + H * OUTD);
    } else {
        for (int e = (bid - 1) * blockDim.x + t; e < N_EDGES; e += (nb - 1) * blockDim.x) {
            int2 sd = load_edge_p(ei, is64, e);
            if ((unsigned)sd.y < N_NODES) atomicAdd(&g_deg[sd.y], 1.0f);
        }
    }
    grid.sync();

    // ---- phase B: feat (reload shared weights; sWin overwritten) ----
    __syncthreads();
    for (int idx = t; idx < DIN * H; idx += blockDim.x) sWin[idx] = Win[idx];
    for (int idx = t; idx < H; idx += blockDim.x) sbin[idx] = bin[idx];
    for (int idx = t; idx < H * OUTD; idx += blockDim.x) sWc[idx] = g_Wc[idx];
    __syncthreads();
    for (int i = bid * blockDim.x + t; i < N_NODES; i += gstride)
        feat_node(i, feat, sWin, sbin, sWc);
    grid.sync();

    // ---- phase C: scatter 1 ----
    for (int e = bid * blockDim.x + t; e < N_EDGES; e += gstride) {
        int2 sd = load_edge_p(ei, is64, e);
        if ((unsigned)sd.x >= N_NODES || (unsigned)sd.y >= N_NODES) continue;
        atomicAdd(&g_acc[sd.y], g_z4[sd.x]);
    }
    grid.sync();

    // ---- phase D: mid ----
    for (int i = bid * blockDim.x + t; i < N_NODES; i += gstride)
        mid_node(i);
    grid.sync();

    // ---- phase E: scatter 2 ----
    for (int e = bid * blockDim.x + t; e < N_EDGES; e += gstride) {
        int2 sd = load_edge_p(ei, is64, e);
        if ((unsigned)sd.x >= N_NODES || (unsigned)sd.y >= N_NODES) continue;
        atomicAdd(&g_acc[sd.y], g_z14[sd.x]);
    }
    grid.sync();

    // ---- phase F: final + invariant restore ----
    for (int i = bid * blockDim.x + t; i < N_NODES; i += gstride)
        final_node(i, out);
}

// ================= fallback path (proven R11 chain) =================
__global__ void __launch_bounds__(384)
k_count(int nEdgeBlocks, const int* A, const int* B,
        const float* __restrict__ W1, const float* __restrict__ W2,
        const float* __restrict__ Wout,
        const float* __restrict__ b1, const float* __restrict__ b2,
        const float* __restrict__ bout) {
    __shared__ int sflags[4];
    __shared__ float sWo[H * OUTD];
    __shared__ float sU [H * OUTD];
    ident_block(A, B, sflags);
    const int* ei;  int is64;  const float* feat;
    if (sflags[0] && !sflags[1]) { ei = A; is64 = sflags[2]; feat = (const float*)B; }
    else                         { ei = B; is64 = sflags[3]; feat = (const float*)A; }
    int t = threadIdx.x;
    if (blockIdx.x == 0 && t == 0) { g_ei_ptr = ei; g_ei64 = is64; g_feat_p = feat; }
    if (blockIdx.x < (unsigned)nEdgeBlocks) {
        int e = blockIdx.x * 384 + t;
        if (e >= N_EDGES) return;
        int d;
        if (is64) d = (int)((const long long*)ei)[N_EDGES + e];
        else      d = ei[N_EDGES + e];
        if ((unsigned)d >= N_NODES) return;
        atomicAdd(&g_deg[d], 1.0f);
        return;
    }
    constants_block(W1, W2, Wout, b1, b2, bout, sWo, sU);
}

__global__ void __launch_bounds__(256)
k_feat(const float* __restrict__ Win, const float* __restrict__ bin) {
    __shared__ __align__(16) float sWin[DIN * H];
    __shared__ __align__(16) float sbin[H];
    __shared__ __align__(16) float sWc[H * OUTD];
    int t = threadIdx.x;
    for (int idx = t; idx < DIN * H; idx += blockDim.x) sWin[idx] = Win[idx];
    for (int idx = t; idx < H; idx += blockDim.x) sbin[idx] = bin[idx];
    for (int idx = t; idx < H * OUTD; idx += blockDim.x) sWc[idx] = g_Wc[idx];
    __syncthreads();
    int i = blockIdx.x * blockDim.x + t;
    if (i < N_NODES) feat_node(i, g_feat_p, sWin, sbin, sWc);
}

__global__ void k_scatter1() {
    int e = blockIdx.x * blockDim.x + threadIdx.x;
    if (e >= N_EDGES) return;
    int2 sd = load_edge_p(g_ei_ptr, g_ei64, e);
    if ((unsigned)sd.x >= N_NODES || (unsigned)sd.y >= N_NODES) return;
    atomicAdd(&g_acc[sd.y], g_z4[sd.x]);
}

__global__ void k_mid() {
    int i = blockIdx.x * blockDim.x + threadIdx.x;
    if (i < N_NODES) mid_node(i);
}

__global__ void k_scatter2() {
    int e = blockIdx.x * blockDim.x + threadIdx.x;
    if (e >= N_EDGES) return;
    int2 sd = load_edge_p(g_ei_ptr, g_ei64, e);
    if ((unsigned)sd.x >= N_NODES || (unsigned)sd.y >= N_NODES) return;
    atomicAdd(&g_acc[sd.y], g_z14[sd.x]);
}

__global__ void k_final(float* __restrict__ out) {
    int i = blockIdx.x * blockDim.x + threadIdx.x;
    if (i < N_NODES) final_node(i, out);
}

// ---------------- launch ----------------
extern "C" void kernel_launch(void* const* d_in, const int* in_sizes, int n_in,
                              void* d_out, int out_size) {
    // ---- size-based scan (order-independent) ----
    const void* cand16[2] = {0, 0}; int n16 = 0;
    const float* W16k[2]  = {0, 0}; int nW  = 0;
    const float* b128[3]  = {0, 0, 0}; int nb = 0;
    const float* Win  = 0;
    const float* Wout = 0;
    const float* bout = 0;
    int pos3 = -1;

    for (int i = 0; i < n_in; i++) {
        switch (in_sizes[i]) {
            case 1600000: if (n16 < 2) cand16[n16++] = d_in[i]; break;
            case 800000:  break;                      // edge_type — unused
            case 2048:    Win  = (const float*)d_in[i]; break;
            case 16384:   if (nW < 2) W16k[nW++] = (const float*)d_in[i]; break;
            case 384:     Wout = (const float*)d_in[i]; break;
            case 128:     if (nb < 3) b128[nb++] = (const float*)d_in[i]; break;
            case 3:       bout = (const float*)d_in[i]; pos3 = i; break;
            default: break;
        }
    }
    const float* W1;
    const float* W2;
    if (pos3 == 0) { W2 = W16k[0]; W1 = W16k[1]; }    // reversed-order convention
    else           { W1 = W16k[0]; W2 = W16k[1]; }
    if (n16 < 2 || nW < 2 || nb < 3 || !Win || !Wout || !bout) {
        cand16[0] = d_in[0]; cand16[1] = d_in[1];
        Win = (const float*)d_in[3]; b128[0] = (const float*)d_in[4];
        W1  = (const float*)d_in[5]; b128[1] = (const float*)d_in[6];
        W2  = (const float*)d_in[7]; b128[2] = (const float*)d_in[8];
        Wout = (const float*)d_in[9]; bout = (const float*)d_in[10];
    }
    const float* bin = b128[0];
    const float* b1  = b128[1];
    const float* b2  = b128[2];
    float* out = (float*)d_out;

    // ---- try cooperative mega-kernel ----
    bool coop_ok = false;
    {
        int dev = 0, sms = 0, perSM = 0, coopAttr = 0;
        cudaGetDevice(&dev);
        cudaDeviceGetAttribute(&sms, cudaDevAttrMultiProcessorCount, dev);
        cudaDeviceGetAttribute(&coopAttr, cudaDevAttrCooperativeLaunch, dev);
        cudaOccupancyMaxActiveBlocksPerMultiprocessor(&perSM, k_mega, 256, 0);
        if (coopAttr && sms > 0 && perSM > 0) {
            int grid = sms * perSM;
            if (grid > 3126) grid = 3126;             // no more than edge work
            cudaLaunchConfig_t cfg = {};
            cfg.gridDim = dim3(grid);
            cfg.blockDim = dim3(256);
            cudaLaunchAttribute attr[1];
            attr[0].id = cudaLaunchAttributeCooperative;
            attr[0].val.cooperative = 1;
            cfg.attrs = attr;
            cfg.numAttrs = 1;
            cudaError_t err = cudaLaunchKernelEx(&cfg, k_mega,
                (const int*)cand16[0], (const int*)cand16[1],
                W1, W2, Wout, b1, b2, bout, Win, bin, out);
            coop_ok = (err == cudaSuccess);
            if (!coop_ok) cudaGetLastError();          // clear sticky error
        }
    }
    if (coop_ok) return;

    // ---- fallback: proven 6-kernel chain ----
    const int TB  = 256;
    const int GN  = (N_NODES + TB - 1) / TB;
    const int GE  = (N_EDGES + TB - 1) / TB;
    const int GE2 = (N_EDGES + 383) / 384;

    k_count<<<GE2 + 1, 384>>>(GE2, (const int*)cand16[0], (const int*)cand16[1],
                              W1, W2, Wout, b1, b2, bout);
    k_feat<<<GN, TB>>>(Win, bin);
    k_scatter1<<<GE, TB>>>();
    k_mid<<<GN, TB>>>();
    k_scatter2<<<GE, TB>>>();
    k_final<<<GN, TB>>>(out);
}